// round 2
// baseline (speedup 1.0000x reference)
#include <cuda_runtime.h>

#define S 2048
#define SMASK 2047
#define NT 1024
#define BATCH 8

static __device__ float g_rho2[BATCH * S];
static __device__ float g_pt[BATCH * S];
static __device__ float g_rhof[BATCH * S];

__device__ __forceinline__ float warp_sum(float v) {
#pragma unroll
    for (int o = 16; o; o >>= 1) v += __shfl_xor_sync(0xffffffffu, v, o);
    return v;
}
__device__ __forceinline__ float warp_max(float v) {
#pragma unroll
    for (int o = 16; o; o >>= 1) v = fmaxf(v, __shfl_xor_sync(0xffffffffu, v, o));
    return v;
}

__device__ float blk_sum(float v, float* scr) {
    int lane = threadIdx.x & 31, wid = threadIdx.x >> 5;
    v = warp_sum(v);
    if (lane == 0) scr[wid] = v;
    __syncthreads();
    if (wid == 0) {
        float t = scr[lane];
        t = warp_sum(t);
        if (lane == 0) scr[32] = t;
    }
    __syncthreads();
    return scr[32];
}

__device__ float blk_max(float v, float* scr) {
    int lane = threadIdx.x & 31, wid = threadIdx.x >> 5;
    v = warp_max(v);
    if (lane == 0) scr[wid] = v;
    __syncthreads();
    if (wid == 0) {
        float t = scr[lane];
        t = warp_max(t);
        if (lane == 0) scr[32] = t;
    }
    __syncthreads();
    return scr[32];
}

// Leray projection: dst = src - grad1(p), p from 50 Jacobi sweeps of lap(p)=div(src).
// Circulant + symmetric => self-adjoint, so it is also its own VJP.
__device__ void leray_fn(float* dst, const float* src, float* bb, float* pA, float* pB) {
    int tid = threadIdx.x;
    for (int i = tid; i < S; i += NT) {
        bb[i] = src[i] - src[(i - 1) & SMASK];
        pA[i] = 0.f;
    }
    __syncthreads();
    float* po = pA;
    float* pn = pB;
#pragma unroll 1
    for (int it = 0; it < 50; ++it) {
        for (int i = tid; i < S; i += NT)
            pn[i] = 0.5f * (po[(i + 1) & SMASK] + po[(i - 1) & SMASK] - bb[i]);
        __syncthreads();
        float* t = po; po = pn; pn = t;
    }
    for (int i = tid; i < S; i += NT)
        dst[i] = src[i] - (po[(i + 1) & SMASK] - po[i]);
    __syncthreads();
}

__device__ __forceinline__ float flux(const float* up, const float* r, int j) {
    float uu = up[j];
    return uu > 0.f ? uu * r[j] : uu * r[(j + 1) & SMASK];
}

// Hand-derived reverse-mode gradient of the MPC cost wrt u. Result left in `up`.
__device__ void grad_cost(const float* u, float* up, const float* rho, const float* v,
                          float* rbuf, float* gg, float* gup,
                          float* bb, float* pA, float* pB, float* scr) {
    int tid = threadIdx.x;
    leray_fn(up, u, bb, pA, pB);
    float lm = 0.f;
    for (int i = tid; i < S; i += NT) lm = fmaxf(lm, fabsf(up[i]));
    float m = blk_max(lm, scr);
    float mp = m + 1e-8f;
    float dt = 0.4f / mp;

    for (int i = tid; i < S; i += NT) rbuf[i] = rho[i];
    __syncthreads();

    float Ts[4];
#pragma unroll 1
    for (int t = 0; t < 4; ++t) {
        float* rt = rbuf + t * S;
        float* rn = rt + S;
        float part = 0.f;
        for (int i = tid; i < S; i += NT) {
            float Fi = flux(up, rt, i);
            float Fm = flux(up, rt, (i - 1) & SMASK);
            float a = rt[i] - dt * (Fi - Fm);
            float z = fabsf(a) + 1e-8f;
            rn[i] = z;
            part += z;
        }
        float T = blk_sum(part, scr);
        Ts[t] = T;
        for (int i = tid; i < S; i += NT) rn[i] = rn[i] / T;
        __syncthreads();
    }

    // backward
    for (int i = tid; i < S; i += NT) {
        gg[i] = (1.f - v[i]) * 0.125f;   // 1/B from jnp.mean
        gup[i] = 0.f;
    }
    __syncthreads();
    float gdt = 0.f;
#pragma unroll 1
    for (int t = 3; t >= 0; --t) {
        float* rt = rbuf + t * S;
        float* rn = rt + S;
        float T = Ts[t];
        float dp = 0.f;
        for (int i = tid; i < S; i += NT) dp += gg[i] * rn[i];
        float dot = blk_sum(dp, scr);
        float gp = 0.f;
        for (int i = tid; i < S; i += NT) {
            float Fi = flux(up, rt, i);
            float Fm = flux(up, rt, (i - 1) & SMASK);
            float df = Fi - Fm;
            float a = rt[i] - dt * df;
            float sg = (a > 0.f) ? 1.f : ((a < 0.f) ? -1.f : 0.f);
            float ga = ((gg[i] - dot) / T) * sg;
            bb[i] = ga;          // stash ga
            gp += ga * df;
        }
        __syncthreads();
        gdt -= blk_sum(gp, scr);
        for (int i = tid; i < S; i += NT) {
            int ip = (i + 1) & SMASK, im = (i - 1) & SMASK;
            float gFi = dt * (bb[ip] - bb[i]);
            float gFm = dt * (bb[i] - bb[im]);
            float upi = up[i], upm = up[im];
            gup[i] += gFi * (upi > 0.f ? rt[i] : rt[ip]);
            float gr = bb[i];
            if (upi > 0.f) gr += gFi * upi;
            if (!(upm > 0.f)) gr += gFm * upm;
            gg[i] = gr;
        }
        __syncthreads();
    }
    float gm = -(0.4f / (mp * mp)) * gdt;
    for (int i = tid; i < S; i += NT) {
        float ui = up[i];
        if (fabsf(ui) == m)
            gup[i] += ((ui > 0.f) ? 1.f : ((ui < 0.f) ? -1.f : 0.f)) * gm;
    }
    __syncthreads();
    leray_fn(up, gup, bb, pA, pB);   // leray is self-adjoint: VJP == leray
}

// ---------------------------------------------------------------------------
// Kernel 1: per-octet 3-level Haar, accumulate coeff^2 over d + per_token dot.
// grid (S/8, B), 256 threads. Reads x once (coalesced), writes tiny arrays.
// ---------------------------------------------------------------------------
__global__ void k_reduce(const float* __restrict__ x, const float* __restrict__ wval) {
    const float IR2 = 0.70710678118654752440f;
    int b = blockIdx.y, g = blockIdx.x, t = threadIdx.x;
    const float* xp = x + ((size_t)(b * S + g * 8)) * 2048;
    float acc[8] = {0, 0, 0, 0, 0, 0, 0, 0};
    float pt[8] = {0, 0, 0, 0, 0, 0, 0, 0};
#pragma unroll
    for (int j = 0; j < 8; ++j) {
        int d = t + j * 256;
        float w = wval[d];
        float xv[8];
#pragma unroll
        for (int k = 0; k < 8; ++k) xv[k] = xp[(size_t)k * 2048 + d];
#pragma unroll
        for (int k = 0; k < 8; ++k) pt[k] += xv[k] * w;
        float a10 = (xv[0] + xv[1]) * IR2, d10 = (xv[0] - xv[1]) * IR2;
        float a11 = (xv[2] + xv[3]) * IR2, d11 = (xv[2] - xv[3]) * IR2;
        float a12 = (xv[4] + xv[5]) * IR2, d12 = (xv[4] - xv[5]) * IR2;
        float a13 = (xv[6] + xv[7]) * IR2, d13 = (xv[6] - xv[7]) * IR2;
        float a20 = (a10 + a11) * IR2, d20 = (a10 - a11) * IR2;
        float a21 = (a12 + a13) * IR2, d21 = (a12 - a13) * IR2;
        float A = (a20 + a21) * IR2, D3 = (a20 - a21) * IR2;
        acc[0] += A * A;   acc[1] += D3 * D3;
        acc[2] += d20 * d20; acc[3] += d21 * d21;
        acc[4] += d10 * d10; acc[5] += d11 * d11;
        acc[6] += d12 * d12; acc[7] += d13 * d13;
    }
    __shared__ float red[8][16];
    int lane = t & 31, wid = t >> 5;
#pragma unroll
    for (int v = 0; v < 8; ++v) {
        float s = warp_sum(acc[v]);
        float q = warp_sum(pt[v]);
        if (lane == 0) { red[wid][v] = s; red[wid][8 + v] = q; }
    }
    __syncthreads();
    if (t < 16) {
        float s = 0.f;
#pragma unroll
        for (int w = 0; w < 8; ++w) s += red[w][t];
        if (t < 8) {
            int pos;
            if (t == 0) pos = g;
            else if (t == 1) pos = 256 + g;
            else if (t == 2) pos = 512 + 2 * g;
            else if (t == 3) pos = 513 + 2 * g;
            else pos = 1024 + 4 * g + (t - 4);
            g_rho2[b * S + pos] = s;
        } else {
            g_pt[b * S + 8 * g + (t - 8)] = s;
        }
    }
}

// ---------------------------------------------------------------------------
// Kernel 2: full dynamical system, one block per batch, all state in smem.
// ---------------------------------------------------------------------------
__global__ void __launch_bounds__(NT) k_dyn(const float* __restrict__ phi) {
    extern __shared__ float smem[];
    float* rho = smem;
    float* v   = smem + 1 * S;
    float* u   = smem + 2 * S;
    float* up  = smem + 3 * S;
    float* bb  = smem + 4 * S;
    float* pA  = smem + 5 * S;
    float* pB  = smem + 6 * S;
    float* gg  = smem + 7 * S;
    float* gup = smem + 8 * S;
    float* phs = smem + 9 * S;
    float* rbuf = smem + 10 * S;  // 5*S
    float* scr = smem + 15 * S;   // 64 floats

    int tid = threadIdx.x, b = blockIdx.x;
    const float IR2 = 0.70710678118654752440f;
    const float SQD = 45.25483399593904156f;  // sqrt(2048)

    // rho = normalize(sqrt(rho2) + eps)
    float part = 0.f;
    for (int i = tid; i < S; i += NT) {
        float rv = sqrtf(g_rho2[b * S + i]) + 1e-8f;
        rho[i] = rv;
        part += rv;
    }
    float T = blk_sum(part, scr);
    for (int i = tid; i < S; i += NT) rho[i] = rho[i] / T;

    // v from per_token: 3-level Haar per octet, |c|*sqrt(D), normalize
    for (int i = tid; i < S; i += NT) pA[i] = g_pt[b * S + i];
    __syncthreads();
    if (tid < 256) {
        int g = tid;
        const float* xx = pA + 8 * g;
        float a10 = (xx[0] + xx[1]) * IR2, d10 = (xx[0] - xx[1]) * IR2;
        float a11 = (xx[2] + xx[3]) * IR2, d11 = (xx[2] - xx[3]) * IR2;
        float a12 = (xx[4] + xx[5]) * IR2, d12 = (xx[4] - xx[5]) * IR2;
        float a13 = (xx[6] + xx[7]) * IR2, d13 = (xx[6] - xx[7]) * IR2;
        float a20 = (a10 + a11) * IR2, d20 = (a10 - a11) * IR2;
        float a21 = (a12 + a13) * IR2, d21 = (a12 - a13) * IR2;
        float A = (a20 + a21) * IR2, D3 = (a20 - a21) * IR2;
        v[g] = fabsf(A) * SQD;
        v[256 + g] = fabsf(D3) * SQD;
        v[512 + 2 * g] = fabsf(d20) * SQD;
        v[513 + 2 * g] = fabsf(d21) * SQD;
        v[1024 + 4 * g + 0] = fabsf(d10) * SQD;
        v[1024 + 4 * g + 1] = fabsf(d11) * SQD;
        v[1024 + 4 * g + 2] = fabsf(d12) * SQD;
        v[1024 + 4 * g + 3] = fabsf(d13) * SQD;
    }
    __syncthreads();
    part = 0.f;
    for (int i = tid; i < S; i += NT) {
        float z = v[i] + 1e-8f;
        pB[i] = z;
        part += z;
    }
    T = blk_sum(part, scr);
    for (int i = tid; i < S; i += NT) v[i] = pB[i] / T;
    for (int i = tid; i < S; i += NT) phs[i] = phi[i];
    __syncthreads();

    const float kap[3] = {0.01f, 0.005f, 0.0f};
#pragma unroll 1
    for (int k = 0; k < 3; ++k) {
        // reaction (1 mirror-descent step)
        part = 0.f;
        for (int i = tid; i < S; i += NT) {
            float gr = phs[i] + logf(rho[i]);
            float val = rho[i] * expf(-0.1f * gr);
            float z = fabsf(val) + 1e-8f;
            pA[i] = z;
            part += z;
        }
        T = blk_sum(part, scr);
        for (int i = tid; i < S; i += NT) rho[i] = pA[i] / T;
        __syncthreads();

        // mpc: 5 inner gradient steps
        for (int i = tid; i < S; i += NT) u[i] = v[(i + 1) & SMASK] - v[i];
        __syncthreads();
#pragma unroll 1
        for (int st = 0; st < 5; ++st) {
            grad_cost(u, up, rho, v, rbuf, gg, gup, bb, pA, pB, scr);
            for (int i = tid; i < S; i += NT) u[i] -= 0.1f * up[i];
            __syncthreads();
        }

        // outer leray + advect with kappa
        leray_fn(up, u, bb, pA, pB);
        float lm = 0.f;
        for (int i = tid; i < S; i += NT) lm = fmaxf(lm, fabsf(up[i]));
        float m = blk_max(lm, scr);
        float dt = 0.4f / (m + 1e-8f);
        float kp = kap[k];
        part = 0.f;
        for (int i = tid; i < S; i += NT) {
            int ip = (i + 1) & SMASK, im = (i - 1) & SMASK;
            float Fi = flux(up, rho, i);
            float Fm = flux(up, rho, im);
            float lap = rho[ip] + rho[im] - 2.f * rho[i];
            float a = rho[i] - dt * (Fi - Fm) + kp * dt * lap;
            float z = fabsf(a) + 1e-8f;
            pA[i] = z;
            part += z;
        }
        T = blk_sum(part, scr);
        for (int i = tid; i < S; i += NT) rho[i] = pA[i] / T;
        __syncthreads();
    }

    // rho_f = normalize(rho + 0.1*v)  (plain normalization, no abs/eps)
    part = 0.f;
    for (int i = tid; i < S; i += NT) {
        float f = rho[i] + 0.1f * v[i];
        pA[i] = f;
        part += f;
    }
    T = blk_sum(part, scr);
    for (int i = tid; i < S; i += NT) g_rhof[b * S + i] = pA[i] / T;
}

// ---------------------------------------------------------------------------
// Kernel 3: out[b,s,d] = sum_j t_j(b,s) * band_w[j,d]  (rank-4 idwt expansion)
// grid (S, B), 256 threads, float4 writes.
// ---------------------------------------------------------------------------
__global__ void k_out(const float* __restrict__ bw, float* __restrict__ out) {
    const float IR2 = 0.70710678118654752440f;
    const float C1 = 0.35355339059327376220f;  // 1/(2*sqrt(2))
    int b = blockIdx.y, s = blockIdx.x, t = threadIdx.x;
    const float* rf = g_rhof + b * S;
    int g = s >> 3, k = s & 7;
    float t0 = rf[g] * C1;
    float t1 = rf[256 + g] * ((k < 4) ? C1 : -C1);
    float t2 = rf[512 + 2 * g + (k >> 2)] * (((k >> 1) & 1) ? -0.5f : 0.5f);
    float t3 = rf[1024 + 4 * g + (k >> 1)] * ((k & 1) ? -IR2 : IR2);

    float4* o = (float4*)(out + ((size_t)(b * S + s)) * 2048);
    const float4* b0 = (const float4*)(bw);
    const float4* b1 = (const float4*)(bw + 2048);
    const float4* b2 = (const float4*)(bw + 4096);
    const float4* b3 = (const float4*)(bw + 6144);
#pragma unroll
    for (int j = t; j < 512; j += 256) {
        float4 w0 = b0[j], w1 = b1[j], w2 = b2[j], w3 = b3[j];
        float4 r;
        r.x = t0 * w0.x + t1 * w1.x + t2 * w2.x + t3 * w3.x;
        r.y = t0 * w0.y + t1 * w1.y + t2 * w2.y + t3 * w3.y;
        r.z = t0 * w0.z + t1 * w1.z + t2 * w2.z + t3 * w3.z;
        r.w = t0 * w0.w + t1 * w1.w + t2 * w2.w + t3 * w3.w;
        o[j] = r;
    }
}

extern "C" void kernel_launch(void* const* d_in, const int* in_sizes, int n_in,
                              void* d_out, int out_size) {
    const float* x = (const float*)d_in[0];
    const float* wval = (const float*)d_in[1];
    const float* phi = (const float*)d_in[2];
    const float* bw = (const float*)d_in[3];
    float* out = (float*)d_out;

    const int smem_bytes = (15 * S + 64) * (int)sizeof(float);
    cudaFuncSetAttribute(k_dyn, cudaFuncAttributeMaxDynamicSharedMemorySize, smem_bytes);

    k_reduce<<<dim3(S / 8, BATCH), 256>>>(x, wval);
    k_dyn<<<BATCH, NT, smem_bytes>>>(phi);
    k_out<<<dim3(S, BATCH), 256>>>(bw, out);
}

// round 5
// speedup vs baseline: 1.8755x; 1.8755x over previous
#include <cuda_runtime.h>

#define S 2048
#define SMASK 2047
#define HMASK 1023
#define NT 1024
#define BATCH 8

static __device__ float g_rho2[BATCH * S];
static __device__ float g_pt[BATCH * S];
static __device__ float g_rhof[BATCH * S];

__device__ __forceinline__ float warp_sum(float v) {
#pragma unroll
    for (int o = 16; o; o >>= 1) v += __shfl_xor_sync(0xffffffffu, v, o);
    return v;
}
__device__ __forceinline__ float warp_max(float v) {
#pragma unroll
    for (int o = 16; o; o >>= 1) v = fmaxf(v, __shfl_xor_sync(0xffffffffu, v, o));
    return v;
}

// Single-sync block reduction into an explicit scratch buffer.
// HAZARD RULE (audited at all call sites): a buffer may be stored to again
// only if at least one __syncthreads separates the new stores from the
// previous reduction's tail-reads of that buffer. Call sites alternate
// scrA/scrB so this always holds.
__device__ __forceinline__ float blk_sum1(float v, float* scr) {
    int lane = threadIdx.x & 31, wid = threadIdx.x >> 5;
    v = warp_sum(v);
    if (lane == 0) scr[wid] = v;
    __syncthreads();
    float t = 0.f;
#pragma unroll
    for (int w = 0; w < 32; ++w) t += scr[w];
    return t;
}
__device__ __forceinline__ float blk_max1(float v, float* scr) {
    int lane = threadIdx.x & 31, wid = threadIdx.x >> 5;
    v = warp_max(v);
    if (lane == 0) scr[wid] = v;
    __syncthreads();
    float t = scr[0];
#pragma unroll
    for (int w = 1; w < 32; ++w) t = fmaxf(t, scr[w]);
    return t;
}

// Leray projection as a 101-tap circulant convolution (exactly equals
// 50 Jacobi sweeps; self-adjoint, so also its own VJP).
// Entry contract: src published (caller synced). Exits with __syncthreads().
__device__ __forceinline__ void leray_conv(float* dst, const float* src,
                                           const float2* wt2, float* lmax) {
    int t = threadIdx.x;                 // outputs 2t, 2t+1
    const float2* U2 = (const float2*)src;
    int t0 = t - 25;                     // float2 index of u[2t-50]
    float s0 = 0.f, s1 = 0.f;
    float2 p0 = U2[t0 & HMASK];
#pragma unroll
    for (int j = 0; j < 52; ++j) {
        float2 wj = wt2[j];
        float2 p1 = U2[(t0 + j + 1) & HMASK];
        s0 += wj.x * p0.x + wj.y * p0.y;
        s1 += wj.x * p0.y + wj.y * p1.x;
        p0 = p1;
    }
    ((float2*)dst)[t] = make_float2(s0, s1);
    if (lmax) *lmax = fmaxf(fabsf(s0), fabsf(s1));
    __syncthreads();
}

__device__ __forceinline__ float flux(const float* up, const float* r, int j) {
    float uu = up[j];
    return uu > 0.f ? uu * r[j] : uu * r[(j + 1) & SMASK];
}

// Hand-derived reverse-mode gradient of the MPC cost wrt u. Result in `up`.
// rbuf: 4*S (normalized post-advect states rn_0..rn_3). rt(0) = rho.
__device__ void grad_cost(const float* u, float* up, const float* rho, const float* v,
                          float* rbuf, float* gg, float* gup, float* bb,
                          float* scrA, float* scrB, const float2* wt2) {
    int tid = threadIdx.x;
    float lm;
    leray_conv(up, u, wt2, &lm);
    float m = blk_max1(lm, scrA);
    float mp = m + 1e-8f;
    float dt = 0.4f / mp;

    float Ts[4];
#pragma unroll 1
    for (int t = 0; t < 4; ++t) {
        const float* rt = (t == 0) ? rho : (rbuf + (t - 1) * S);
        float* rn = rbuf + t * S;
        float part = 0.f;
        for (int i = tid; i < S; i += NT) {
            float Fi = flux(up, rt, i);
            float Fm = flux(up, rt, (i - 1) & SMASK);
            float a = rt[i] - dt * (Fi - Fm);
            float z = fabsf(a) + 1e-8f;
            rn[i] = z;
            part += z;
        }
        float T = blk_sum1(part, (t & 1) ? scrA : scrB);
        Ts[t] = T;
        for (int i = tid; i < S; i += NT) rn[i] = rn[i] / T;
        __syncthreads();                   // publish normalized rn for step t+1 stencil
    }

    // backward (gg, gup, bb stores are same-owner; publication via blk_sum syncs)
    for (int i = tid; i < S; i += NT) {
        gg[i] = (1.f - v[i]) * 0.125f;     // 1/B from jnp.mean
        gup[i] = 0.f;
    }
    float gdt = 0.f;
#pragma unroll 1
    for (int t = 3; t >= 0; --t) {
        const float* rt = (t == 0) ? rho : (rbuf + (t - 1) * S);
        const float* rn = rbuf + t * S;
        float T = Ts[t];
        float dp = 0.f;
        for (int i = tid; i < S; i += NT) dp += gg[i] * rn[i];
        float dot = blk_sum1(dp, scrB);
        float gp = 0.f;
        for (int i = tid; i < S; i += NT) {
            float Fi = flux(up, rt, i);
            float Fm = flux(up, rt, (i - 1) & SMASK);
            float df = Fi - Fm;
            float a = rt[i] - dt * df;
            float sg = (a > 0.f) ? 1.f : ((a < 0.f) ? -1.f : 0.f);
            float ga = ((gg[i] - dot) / T) * sg;
            bb[i] = ga;
            gp += ga * df;
        }
        gdt -= blk_sum1(gp, scrA);         // this sync also publishes bb
        for (int i = tid; i < S; i += NT) {
            int ip = (i + 1) & SMASK, im = (i - 1) & SMASK;
            float gFi = dt * (bb[ip] - bb[i]);
            float gFm = dt * (bb[i] - bb[im]);
            float upi = up[i], upm = up[im];
            gup[i] += gFi * (upi > 0.f ? rt[i] : rt[ip]);
            float gr = bb[i];
            if (upi > 0.f) gr += gFi * upi;
            if (!(upm > 0.f)) gr += gFm * upm;
            gg[i] = gr;
        }
    }
    float gm = -(0.4f / (mp * mp)) * gdt;
    for (int i = tid; i < S; i += NT) {
        float ui = up[i];
        if (fabsf(ui) == m)
            gup[i] += ((ui > 0.f) ? 1.f : ((ui < 0.f) ? -1.f : 0.f)) * gm;
    }
    __syncthreads();                       // publish gup for conv
    leray_conv(up, gup, wt2, 0);           // self-adjoint: VJP == leray
}

// ---------------------------------------------------------------------------
// Kernel 1: per-octet 3-level Haar, accumulate coeff^2 over d + per_token dot.
// Streaming float4 loads. grid (S/8, B), 256 threads.
// ---------------------------------------------------------------------------
__global__ void k_reduce(const float* __restrict__ x, const float* __restrict__ wval) {
    const float IR2 = 0.70710678118654752440f;
    int b = blockIdx.y, g = blockIdx.x, t = threadIdx.x;
    const float4* X4 = (const float4*)(x + ((size_t)(b * S + g * 8)) * 2048);
    const float4* W4 = (const float4*)wval;
    float acc[8] = {0, 0, 0, 0, 0, 0, 0, 0};
    float pt[8] = {0, 0, 0, 0, 0, 0, 0, 0};

#define HAARC(C)                                                              \
    do {                                                                      \
        float q0 = xv[0].C, q1 = xv[1].C, q2 = xv[2].C, q3 = xv[3].C;         \
        float q4 = xv[4].C, q5 = xv[5].C, q6 = xv[6].C, q7 = xv[7].C;         \
        float wc = w4.C;                                                      \
        pt[0] += q0 * wc; pt[1] += q1 * wc; pt[2] += q2 * wc; pt[3] += q3 * wc;\
        pt[4] += q4 * wc; pt[5] += q5 * wc; pt[6] += q6 * wc; pt[7] += q7 * wc;\
        float a10 = (q0 + q1) * IR2, d10 = (q0 - q1) * IR2;                   \
        float a11 = (q2 + q3) * IR2, d11 = (q2 - q3) * IR2;                   \
        float a12 = (q4 + q5) * IR2, d12 = (q4 - q5) * IR2;                   \
        float a13 = (q6 + q7) * IR2, d13 = (q6 - q7) * IR2;                   \
        float a20 = (a10 + a11) * IR2, d20 = (a10 - a11) * IR2;               \
        float a21 = (a12 + a13) * IR2, d21 = (a12 - a13) * IR2;               \
        float A = (a20 + a21) * IR2, D3 = (a20 - a21) * IR2;                  \
        acc[0] += A * A;     acc[1] += D3 * D3;                               \
        acc[2] += d20 * d20; acc[3] += d21 * d21;                             \
        acc[4] += d10 * d10; acc[5] += d11 * d11;                             \
        acc[6] += d12 * d12; acc[7] += d13 * d13;                             \
    } while (0)

#pragma unroll
    for (int h = 0; h < 2; ++h) {
        int d4 = t + h * 256;
        float4 w4 = W4[d4];
        float4 xv[8];
#pragma unroll
        for (int k = 0; k < 8; ++k) xv[k] = __ldcs(&X4[k * 512 + d4]);
        HAARC(x); HAARC(y); HAARC(z); HAARC(w);
    }
#undef HAARC

    __shared__ float red[8][16];
    int lane = t & 31, wid = t >> 5;
#pragma unroll
    for (int v = 0; v < 8; ++v) {
        float s = warp_sum(acc[v]);
        float q = warp_sum(pt[v]);
        if (lane == 0) { red[wid][v] = s; red[wid][8 + v] = q; }
    }
    __syncthreads();
    if (t < 16) {
        float s = 0.f;
#pragma unroll
        for (int w = 0; w < 8; ++w) s += red[w][t];
        if (t < 8) {
            int pos;
            if (t == 0) pos = g;
            else if (t == 1) pos = 256 + g;
            else if (t == 2) pos = 512 + 2 * g;
            else if (t == 3) pos = 513 + 2 * g;
            else pos = 1024 + 4 * g + (t - 4);
            g_rho2[b * S + pos] = s;
        } else {
            g_pt[b * S + 8 * g + (t - 8)] = s;
        }
    }
}

// ---------------------------------------------------------------------------
// Kernel 2: full dynamical system, one block per batch, all state in smem.
// ---------------------------------------------------------------------------
__global__ void __launch_bounds__(NT) k_dyn(const float* __restrict__ phi) {
    extern __shared__ float smem[];
    float* rho = smem;
    float* v   = smem + 1 * S;
    float* u   = smem + 2 * S;
    float* up  = smem + 3 * S;
    float* bb  = smem + 4 * S;
    float* pA  = smem + 5 * S;
    float* pB  = smem + 6 * S;
    float* gg  = smem + 7 * S;
    float* gup = smem + 8 * S;
    float* phs = smem + 9 * S;
    float* rbuf = smem + 10 * S;        // 4*S (rn_0..rn_3)
    float* scrA = smem + 14 * S;        // 32 floats
    float* scrB = smem + 14 * S + 32;   // 32 floats
    float* wt  = smem + 14 * S + 64;    // 104 floats (Leray conv taps, padded)
    const float2* wt2 = (const float2*)wt;

    int tid = threadIdx.x, b = blockIdx.x;
    const float IR2 = 0.70710678118654752440f;
    const float SQD = 45.25483399593904156f;  // sqrt(2048)

    // ---- Leray conv taps: c[k] = -0.5 * sum_{j=|k|..49, j==k mod 2} C(j,(j+k)/2)/2^j
    //      w(off) = delta - (c[off-1] - 2c[off] + c[off+1]), support +-50.
    {
        float* cc = bb;                 // bb free here; cc[0..98], k = idx-49
        if (tid < 99) {
            int k = tid - 49;
            int ak = (k < 0) ? -k : k;
            float term = exp2f(-(float)ak);   // C(ak,ak)/2^ak
            float sum = 0.f;
            for (int j = ak; j <= 49; j += 2) {
                sum += term;
                float num = (float)(j + 1) * (float)(j + 2);
                float den = 4.f * (float)((j + k) / 2 + 1) * (float)((j - k) / 2 + 1);
                term *= num / den;
            }
            cc[tid] = -0.5f * sum;
        }
        __syncthreads();
        if (tid < 104) {
            float val = 0.f;
            if (tid <= 100) {
                int m = tid - 50;
                float cm1 = (m - 1 >= -49 && m - 1 <= 49) ? cc[m - 1 + 49] : 0.f;
                float c0  = (m     >= -49 && m     <= 49) ? cc[m + 49]     : 0.f;
                float cp1 = (m + 1 >= -49 && m + 1 <= 49) ? cc[m + 1 + 49] : 0.f;
                val = ((m == 0) ? 1.f : 0.f) - (cm1 - 2.f * c0 + cp1);
            }
            wt[tid] = val;
        }
        __syncthreads();
    }

    // rho = normalize(sqrt(rho2) + eps)
    float part = 0.f;
    for (int i = tid; i < S; i += NT) {
        float rv = sqrtf(g_rho2[b * S + i]) + 1e-8f;
        rho[i] = rv;
        part += rv;
    }
    float T = blk_sum1(part, scrA);
    for (int i = tid; i < S; i += NT) rho[i] = rho[i] / T;

    // v from per_token: 3-level Haar per octet, |c|*sqrt(D), normalize
    for (int i = tid; i < S; i += NT) pA[i] = g_pt[b * S + i];
    __syncthreads();                       // publish pA for haar
    if (tid < 256) {
        int g = tid;
        const float* xx = pA + 8 * g;
        float a10 = (xx[0] + xx[1]) * IR2, d10 = (xx[0] - xx[1]) * IR2;
        float a11 = (xx[2] + xx[3]) * IR2, d11 = (xx[2] - xx[3]) * IR2;
        float a12 = (xx[4] + xx[5]) * IR2, d12 = (xx[4] - xx[5]) * IR2;
        float a13 = (xx[6] + xx[7]) * IR2, d13 = (xx[6] - xx[7]) * IR2;
        float a20 = (a10 + a11) * IR2, d20 = (a10 - a11) * IR2;
        float a21 = (a12 + a13) * IR2, d21 = (a12 - a13) * IR2;
        float A = (a20 + a21) * IR2, D3 = (a20 - a21) * IR2;
        v[g] = fabsf(A) * SQD;
        v[256 + g] = fabsf(D3) * SQD;
        v[512 + 2 * g] = fabsf(d20) * SQD;
        v[513 + 2 * g] = fabsf(d21) * SQD;
        v[1024 + 4 * g + 0] = fabsf(d10) * SQD;
        v[1024 + 4 * g + 1] = fabsf(d11) * SQD;
        v[1024 + 4 * g + 2] = fabsf(d12) * SQD;
        v[1024 + 4 * g + 3] = fabsf(d13) * SQD;
    }
    __syncthreads();                       // publish raw v
    part = 0.f;
    for (int i = tid; i < S; i += NT) {
        float z = v[i] + 1e-8f;
        pB[i] = z;
        part += z;
    }
    T = blk_sum1(part, scrB);
    for (int i = tid; i < S; i += NT) v[i] = pB[i] / T;   // same-owner
    for (int i = tid; i < S; i += NT) phs[i] = phi[i];    // same-owner

    const float kap[3] = {0.01f, 0.005f, 0.0f};
#pragma unroll 1
    for (int k = 0; k < 3; ++k) {
        // reaction (1 mirror-descent step); rho stores same-owner
        part = 0.f;
        for (int i = tid; i < S; i += NT) {
            float gr = phs[i] + logf(rho[i]);
            float val = rho[i] * expf(-0.1f * gr);
            float z = fabsf(val) + 1e-8f;
            pA[i] = z;
            part += z;
        }
        T = blk_sum1(part, scrA);          // sync also publishes normalized v (k=0)
        for (int i = tid; i < S; i += NT) rho[i] = pA[i] / T;

        // mpc: 5 inner gradient steps
        for (int i = tid; i < S; i += NT) u[i] = v[(i + 1) & SMASK] - v[i];
        __syncthreads();                   // publish u AND rho
#pragma unroll 1
        for (int st = 0; st < 5; ++st) {
            grad_cost(u, up, rho, v, rbuf, gg, gup, bb, scrA, scrB, wt2);
            for (int i = tid; i < S; i += NT) u[i] -= 0.1f * up[i];
            __syncthreads();               // publish u
        }

        // outer leray + advect with kappa
        float lm;
        leray_conv(up, u, wt2, &lm);
        float m = blk_max1(lm, scrA);
        float dt = 0.4f / (m + 1e-8f);
        float kp = kap[k];
        part = 0.f;
        for (int i = tid; i < S; i += NT) {
            int ip = (i + 1) & SMASK, im = (i - 1) & SMASK;
            float Fi = flux(up, rho, i);
            float Fm = flux(up, rho, im);
            float lap = rho[ip] + rho[im] - 2.f * rho[i];
            float a = rho[i] - dt * (Fi - Fm) + kp * dt * lap;
            float z = fabsf(a) + 1e-8f;
            pA[i] = z;
            part += z;
        }
        T = blk_sum1(part, scrB);
        for (int i = tid; i < S; i += NT) rho[i] = pA[i] / T;   // same-owner
    }

    // rho_f = normalize(rho + 0.1*v)
    part = 0.f;
    for (int i = tid; i < S; i += NT) {
        float f = rho[i] + 0.1f * v[i];
        pA[i] = f;
        part += f;
    }
    T = blk_sum1(part, scrA);
    for (int i = tid; i < S; i += NT) g_rhof[b * S + i] = pA[i] / T;
}

// ---------------------------------------------------------------------------
// Kernel 3: out[b,s,d] = sum_j t_j(b,s) * band_w[j,d]  (rank-4 idwt expansion)
// ---------------------------------------------------------------------------
__global__ void k_out(const float* __restrict__ bw, float* __restrict__ out) {
    const float IR2 = 0.70710678118654752440f;
    const float C1 = 0.35355339059327376220f;  // 1/(2*sqrt(2))
    int b = blockIdx.y, s = blockIdx.x, t = threadIdx.x;
    const float* rf = g_rhof + b * S;
    int g = s >> 3, k = s & 7;
    float t0 = rf[g] * C1;
    float t1 = rf[256 + g] * ((k < 4) ? C1 : -C1);
    float t2 = rf[512 + 2 * g + (k >> 2)] * (((k >> 1) & 1) ? -0.5f : 0.5f);
    float t3 = rf[1024 + 4 * g + (k >> 1)] * ((k & 1) ? -IR2 : IR2);

    float4* o = (float4*)(out + ((size_t)(b * S + s)) * 2048);
    const float4* b0 = (const float4*)(bw);
    const float4* b1 = (const float4*)(bw + 2048);
    const float4* b2 = (const float4*)(bw + 4096);
    const float4* b3 = (const float4*)(bw + 6144);
#pragma unroll
    for (int j = t; j < 512; j += 256) {
        float4 w0 = b0[j], w1 = b1[j], w2 = b2[j], w3 = b3[j];
        float4 r;
        r.x = t0 * w0.x + t1 * w1.x + t2 * w2.x + t3 * w3.x;
        r.y = t0 * w0.y + t1 * w1.y + t2 * w2.y + t3 * w3.y;
        r.z = t0 * w0.z + t1 * w1.z + t2 * w2.z + t3 * w3.z;
        r.w = t0 * w0.w + t1 * w1.w + t2 * w2.w + t3 * w3.w;
        __stcs(&o[j], r);
    }
}

extern "C" void kernel_launch(void* const* d_in, const int* in_sizes, int n_in,
                              void* d_out, int out_size) {
    const float* x = (const float*)d_in[0];
    const float* wval = (const float*)d_in[1];
    const float* phi = (const float*)d_in[2];
    const float* bw = (const float*)d_in[3];
    float* out = (float*)d_out;

    const int smem_bytes = (14 * S + 64 + 104) * (int)sizeof(float);
    cudaFuncSetAttribute(k_dyn, cudaFuncAttributeMaxDynamicSharedMemorySize, smem_bytes);

    k_reduce<<<dim3(S / 8, BATCH), 256>>>(x, wval);
    k_dyn<<<BATCH, NT, smem_bytes>>>(phi);
    k_out<<<dim3(S, BATCH), 256>>>(bw, out);
}

// round 6
// speedup vs baseline: 2.2332x; 1.1907x over previous
#include <cuda_runtime.h>

#define S 2048
#define SMASK 2047
#define HMASK 1023
#define NT 1024
#define BATCH 8

static __device__ float g_rho2[BATCH * S];
static __device__ float g_pt[BATCH * S];
static __device__ float g_rhof[BATCH * S];

__device__ __forceinline__ float warp_sum(float v) {
#pragma unroll
    for (int o = 16; o; o >>= 1) v += __shfl_xor_sync(0xffffffffu, v, o);
    return v;
}
__device__ __forceinline__ float warp_max(float v) {
#pragma unroll
    for (int o = 16; o; o >>= 1) v = fmaxf(v, __shfl_xor_sync(0xffffffffu, v, o));
    return v;
}

// Single-sync block reduction into an explicit scratch buffer.
// HAZARD RULE (audited at all call sites): a buffer may be stored to again
// only if at least one __syncthreads separates the new stores from the
// previous reduction's tail-reads of that buffer. Call sites alternate
// scrA/scrB so this always holds.
__device__ __forceinline__ float blk_sum1(float v, float* scr) {
    int lane = threadIdx.x & 31, wid = threadIdx.x >> 5;
    v = warp_sum(v);
    if (lane == 0) scr[wid] = v;
    __syncthreads();
    float t = 0.f;
#pragma unroll
    for (int w = 0; w < 32; ++w) t += scr[w];
    return t;
}
__device__ __forceinline__ float blk_max1(float v, float* scr) {
    int lane = threadIdx.x & 31, wid = threadIdx.x >> 5;
    v = warp_max(v);
    if (lane == 0) scr[wid] = v;
    __syncthreads();
    float t = scr[0];
#pragma unroll
    for (int w = 1; w < 32; ++w) t = fmaxf(t, scr[w]);
    return t;
}

// Leray projection. Fourier identity: 50 Jacobi sweeps of lap(p)=div(u) followed
// by u - grad(p) has symbol exactly cos^50(theta) == A^50, A = (S+ + S-)/2.
// => binomial filter w[j] = C(50,25+j)/2^50 at EVEN offsets 2j, truncated at
// |j|<=18 (tail mass ~4e-8). Even/odd lanes decouple: one float2 load feeds
// both components; symmetric taps allow add-before-multiply.
// Self-adjoint (symmetric) => also its own VJP.
// Entry contract: src published (caller synced). Exits with __syncthreads().
__device__ __forceinline__ void leray_conv(float* dst, const float* src,
                                           const float* ws, float* lmax) {
    int t = threadIdx.x;                 // outputs 2t, 2t+1
    const float2* U2 = (const float2*)src;
    float2 c = U2[t];
    float s0 = ws[0] * c.x, s1 = ws[0] * c.y;
#pragma unroll
    for (int j = 1; j <= 18; ++j) {
        float2 a = U2[(t + j) & HMASK];
        float2 b = U2[(t - j) & HMASK];
        float wj = ws[j];
        s0 += wj * (a.x + b.x);
        s1 += wj * (a.y + b.y);
    }
    ((float2*)dst)[t] = make_float2(s0, s1);
    if (lmax) *lmax = fmaxf(fabsf(s0), fabsf(s1));
    __syncthreads();
}

// Hand-derived reverse-mode gradient of the MPC cost wrt u. Result in `up`.
// zb: 4*S unnormalized post-advect magnitudes z_0..z_3 (lazy normalization:
// normalized value = z * (1/T), applied at point of use — exact modulo 1 ulp).
__device__ void grad_cost(const float* u, float* up, const float* rho, const float* v,
                          float* zb, float* gg, float* gup, float* bb,
                          float* scrA, float* scrB, const float* ws) {
    int tid = threadIdx.x;
    float lm;
    leray_conv(up, u, ws, &lm);
    float m = blk_max1(lm, scrA);
    float mp = m + 1e-8f;
    float dt = 0.4f / mp;

    float Ts[4], invT[4];
#pragma unroll 1
    for (int t = 0; t < 4; ++t) {
        const float* zp = (t == 0) ? rho : (zb + (t - 1) * S);
        float inv = (t == 0) ? 1.f : invT[t - 1];
        float* zn = zb + t * S;
        float part = 0.f;
        for (int i = tid; i < S; i += NT) {
            int ip = (i + 1) & SMASK, im = (i - 1) & SMASK;
            float ri = zp[i] * inv, rip = zp[ip] * inv, rim = zp[im] * inv;
            float upi = up[i], upm = up[im];
            float Fi = upi > 0.f ? upi * ri : upi * rip;
            float Fm = upm > 0.f ? upm * rim : upm * ri;
            float a = ri - dt * (Fi - Fm);
            float z = fabsf(a) + 1e-8f;
            zn[i] = z;
            part += z;
        }
        float T = blk_sum1(part, (t & 1) ? scrA : scrB);  // sync publishes zn
        Ts[t] = T;
        invT[t] = 1.f / T;
    }

    // backward init: gg, gup, and the dot for step t=3 fused in one pass
    float dp = 0.f;
    {
        float i3 = invT[3];
        const float* z3 = zb + 3 * S;
        for (int i = tid; i < S; i += NT) {
            float g0 = (1.f - v[i]) * 0.125f;   // 1/B from jnp.mean
            gg[i] = g0;
            gup[i] = 0.f;
            dp += g0 * (z3[i] * i3);
        }
    }
    float dot = blk_sum1(dp, scrB);
    float gdt = 0.f;
#pragma unroll 1
    for (int t = 3; t >= 0; --t) {
        const float* rtp = (t == 0) ? rho : (zb + (t - 1) * S);
        float invp = (t == 0) ? 1.f : invT[t - 1];
        float T = Ts[t];
        float gp = 0.f;
        for (int i = tid; i < S; i += NT) {
            int ip = (i + 1) & SMASK, im = (i - 1) & SMASK;
            float ri = rtp[i] * invp, rip = rtp[ip] * invp, rim = rtp[im] * invp;
            float upi = up[i], upm = up[im];
            float Fi = upi > 0.f ? upi * ri : upi * rip;
            float Fm = upm > 0.f ? upm * rim : upm * ri;
            float df = Fi - Fm;
            float a = ri - dt * df;
            float sg = (a > 0.f) ? 1.f : ((a < 0.f) ? -1.f : 0.f);
            float ga = ((gg[i] - dot) / T) * sg;
            bb[i] = ga;
            gp += ga * df;
        }
        gdt -= blk_sum1(gp, scrA);          // sync publishes bb
        float dpn = 0.f;
        for (int i = tid; i < S; i += NT) {
            int ip = (i + 1) & SMASK, im = (i - 1) & SMASK;
            float gFi = dt * (bb[ip] - bb[i]);
            float gFm = dt * (bb[i] - bb[im]);
            float upi = up[i], upm = up[im];
            float rni = rtp[i] * invp;
            gup[i] += gFi * (upi > 0.f ? rni : rtp[ip] * invp);
            float gr = bb[i];
            if (upi > 0.f) gr += gFi * upi;
            if (!(upm > 0.f)) gr += gFm * upm;
            gg[i] = gr;
            if (t > 0) dpn += gr * rni;     // dot for step t-1: rn_{t-1} == rt_norm
        }
        if (t > 0) dot = blk_sum1(dpn, scrB);
        // t==0: no sync — gup/gg stores are same-owner with the argmax fold below
    }
    float gm = -(0.4f / (mp * mp)) * gdt;
    for (int i = tid; i < S; i += NT) {
        float ui = up[i];
        if (fabsf(ui) == m)
            gup[i] += ((ui > 0.f) ? 1.f : ((ui < 0.f) ? -1.f : 0.f)) * gm;
    }
    __syncthreads();                        // publish gup for conv
    leray_conv(up, gup, ws, 0);             // self-adjoint: VJP == leray
}

// ---------------------------------------------------------------------------
// Kernel 1: per-octet 3-level Haar, accumulate coeff^2 over d + per_token dot.
// Streaming float4 loads. grid (S/8, B), 256 threads.
// ---------------------------------------------------------------------------
__global__ void k_reduce(const float* __restrict__ x, const float* __restrict__ wval) {
    const float IR2 = 0.70710678118654752440f;
    int b = blockIdx.y, g = blockIdx.x, t = threadIdx.x;
    const float4* X4 = (const float4*)(x + ((size_t)(b * S + g * 8)) * 2048);
    const float4* W4 = (const float4*)wval;
    float acc[8] = {0, 0, 0, 0, 0, 0, 0, 0};
    float pt[8] = {0, 0, 0, 0, 0, 0, 0, 0};

#define HAARC(C)                                                              \
    do {                                                                      \
        float q0 = xv[0].C, q1 = xv[1].C, q2 = xv[2].C, q3 = xv[3].C;         \
        float q4 = xv[4].C, q5 = xv[5].C, q6 = xv[6].C, q7 = xv[7].C;         \
        float wc = w4.C;                                                      \
        pt[0] += q0 * wc; pt[1] += q1 * wc; pt[2] += q2 * wc; pt[3] += q3 * wc;\
        pt[4] += q4 * wc; pt[5] += q5 * wc; pt[6] += q6 * wc; pt[7] += q7 * wc;\
        float a10 = (q0 + q1) * IR2, d10 = (q0 - q1) * IR2;                   \
        float a11 = (q2 + q3) * IR2, d11 = (q2 - q3) * IR2;                   \
        float a12 = (q4 + q5) * IR2, d12 = (q4 - q5) * IR2;                   \
        float a13 = (q6 + q7) * IR2, d13 = (q6 - q7) * IR2;                   \
        float a20 = (a10 + a11) * IR2, d20 = (a10 - a11) * IR2;               \
        float a21 = (a12 + a13) * IR2, d21 = (a12 - a13) * IR2;               \
        float A = (a20 + a21) * IR2, D3 = (a20 - a21) * IR2;                  \
        acc[0] += A * A;     acc[1] += D3 * D3;                               \
        acc[2] += d20 * d20; acc[3] += d21 * d21;                             \
        acc[4] += d10 * d10; acc[5] += d11 * d11;                             \
        acc[6] += d12 * d12; acc[7] += d13 * d13;                             \
    } while (0)

#pragma unroll
    for (int h = 0; h < 2; ++h) {
        int d4 = t + h * 256;
        float4 w4 = W4[d4];
        float4 xv[8];
#pragma unroll
        for (int k = 0; k < 8; ++k) xv[k] = __ldcs(&X4[k * 512 + d4]);
        HAARC(x); HAARC(y); HAARC(z); HAARC(w);
    }
#undef HAARC

    __shared__ float red[8][16];
    int lane = t & 31, wid = t >> 5;
#pragma unroll
    for (int v = 0; v < 8; ++v) {
        float s = warp_sum(acc[v]);
        float q = warp_sum(pt[v]);
        if (lane == 0) { red[wid][v] = s; red[wid][8 + v] = q; }
    }
    __syncthreads();
    if (t < 16) {
        float s = 0.f;
#pragma unroll
        for (int w = 0; w < 8; ++w) s += red[w][t];
        if (t < 8) {
            int pos;
            if (t == 0) pos = g;
            else if (t == 1) pos = 256 + g;
            else if (t == 2) pos = 512 + 2 * g;
            else if (t == 3) pos = 513 + 2 * g;
            else pos = 1024 + 4 * g + (t - 4);
            g_rho2[b * S + pos] = s;
        } else {
            g_pt[b * S + 8 * g + (t - 8)] = s;
        }
    }
}

// ---------------------------------------------------------------------------
// Kernel 2: full dynamical system, one block per batch, all state in smem.
// ---------------------------------------------------------------------------
__global__ void __launch_bounds__(NT) k_dyn(const float* __restrict__ phi) {
    extern __shared__ float smem[];
    float* rho = smem;
    float* v   = smem + 1 * S;
    float* u   = smem + 2 * S;
    float* up  = smem + 3 * S;
    float* bb  = smem + 4 * S;
    float* pA  = smem + 5 * S;
    float* pB  = smem + 6 * S;
    float* gg  = smem + 7 * S;
    float* gup = smem + 8 * S;
    float* phs = smem + 9 * S;
    float* zb  = smem + 10 * S;         // 4*S (z_0..z_3, unnormalized)
    float* scrA = smem + 14 * S;        // 32 floats
    float* scrB = smem + 14 * S + 32;   // 32 floats
    float* ws  = smem + 14 * S + 64;    // 20 floats (binomial Leray taps)

    int tid = threadIdx.x, b = blockIdx.x;
    const float IR2 = 0.70710678118654752440f;
    const float SQD = 45.25483399593904156f;  // sqrt(2048)

    // Leray taps: w[j] = C(50,25+j)/2^50, j=0..18 (exact binomial recurrence).
    if (tid == 0) {
        double w = 0.11227517265921705;   // C(50,25)/2^50
        for (int j = 0; j <= 18; ++j) {
            ws[j] = (float)w;
            w *= (double)(25 - j) / (double)(26 + j);
        }
    }
    __syncthreads();

    // rho = normalize(sqrt(rho2) + eps)
    float part = 0.f;
    for (int i = tid; i < S; i += NT) {
        float rv = sqrtf(g_rho2[b * S + i]) + 1e-8f;
        rho[i] = rv;
        part += rv;
    }
    float T = blk_sum1(part, scrA);
    for (int i = tid; i < S; i += NT) rho[i] = rho[i] / T;

    // v from per_token: 3-level Haar per octet, |c|*sqrt(D), normalize
    for (int i = tid; i < S; i += NT) pA[i] = g_pt[b * S + i];
    __syncthreads();                       // publish pA for haar
    if (tid < 256) {
        int g = tid;
        const float* xx = pA + 8 * g;
        float a10 = (xx[0] + xx[1]) * IR2, d10 = (xx[0] - xx[1]) * IR2;
        float a11 = (xx[2] + xx[3]) * IR2, d11 = (xx[2] - xx[3]) * IR2;
        float a12 = (xx[4] + xx[5]) * IR2, d12 = (xx[4] - xx[5]) * IR2;
        float a13 = (xx[6] + xx[7]) * IR2, d13 = (xx[6] - xx[7]) * IR2;
        float a20 = (a10 + a11) * IR2, d20 = (a10 - a11) * IR2;
        float a21 = (a12 + a13) * IR2, d21 = (a12 - a13) * IR2;
        float A = (a20 + a21) * IR2, D3 = (a20 - a21) * IR2;
        v[g] = fabsf(A) * SQD;
        v[256 + g] = fabsf(D3) * SQD;
        v[512 + 2 * g] = fabsf(d20) * SQD;
        v[513 + 2 * g] = fabsf(d21) * SQD;
        v[1024 + 4 * g + 0] = fabsf(d10) * SQD;
        v[1024 + 4 * g + 1] = fabsf(d11) * SQD;
        v[1024 + 4 * g + 2] = fabsf(d12) * SQD;
        v[1024 + 4 * g + 3] = fabsf(d13) * SQD;
    }
    __syncthreads();                       // publish raw v
    part = 0.f;
    for (int i = tid; i < S; i += NT) {
        float z = v[i] + 1e-8f;
        pB[i] = z;
        part += z;
    }
    T = blk_sum1(part, scrB);
    for (int i = tid; i < S; i += NT) v[i] = pB[i] / T;   // same-owner
    for (int i = tid; i < S; i += NT) phs[i] = phi[i];    // same-owner

    const float kap[3] = {0.01f, 0.005f, 0.0f};
#pragma unroll 1
    for (int k = 0; k < 3; ++k) {
        // reaction (1 mirror-descent step); rho stores same-owner
        part = 0.f;
        for (int i = tid; i < S; i += NT) {
            float gr = phs[i] + logf(rho[i]);
            float val = rho[i] * expf(-0.1f * gr);
            float z = fabsf(val) + 1e-8f;
            pA[i] = z;
            part += z;
        }
        T = blk_sum1(part, scrA);          // sync also publishes normalized v (k=0)
        for (int i = tid; i < S; i += NT) rho[i] = pA[i] / T;

        // mpc: 5 inner gradient steps
        for (int i = tid; i < S; i += NT) u[i] = v[(i + 1) & SMASK] - v[i];
        __syncthreads();                   // publish u AND rho
#pragma unroll 1
        for (int st = 0; st < 5; ++st) {
            grad_cost(u, up, rho, v, zb, gg, gup, bb, scrA, scrB, ws);
            // float2 same-owner with conv output: no pre-sync needed
            float2* u2 = (float2*)u;
            const float2* up2 = (const float2*)up;
            float2 uu = u2[tid], dd = up2[tid];
            u2[tid] = make_float2(uu.x - 0.1f * dd.x, uu.y - 0.1f * dd.y);
            __syncthreads();               // publish u
        }

        // outer leray + advect with kappa
        float lm;
        leray_conv(up, u, ws, &lm);
        float m = blk_max1(lm, scrA);
        float dt = 0.4f / (m + 1e-8f);
        float kp = kap[k];
        part = 0.f;
        for (int i = tid; i < S; i += NT) {
            int ip = (i + 1) & SMASK, im = (i - 1) & SMASK;
            float upi = up[i], upm = up[im];
            float Fi = upi > 0.f ? upi * rho[i] : upi * rho[ip];
            float Fm = upm > 0.f ? upm * rho[im] : upm * rho[i];
            float lap = rho[ip] + rho[im] - 2.f * rho[i];
            float a = rho[i] - dt * (Fi - Fm) + kp * dt * lap;
            float z = fabsf(a) + 1e-8f;
            pA[i] = z;
            part += z;
        }
        T = blk_sum1(part, scrB);
        for (int i = tid; i < S; i += NT) rho[i] = pA[i] / T;   // same-owner
    }

    // rho_f = normalize(rho + 0.1*v)
    part = 0.f;
    for (int i = tid; i < S; i += NT) {
        float f = rho[i] + 0.1f * v[i];
        pA[i] = f;
        part += f;
    }
    T = blk_sum1(part, scrA);
    for (int i = tid; i < S; i += NT) g_rhof[b * S + i] = pA[i] / T;
}

// ---------------------------------------------------------------------------
// Kernel 3: out[b,s,d] = sum_j t_j(b,s) * band_w[j,d]  (rank-4 idwt expansion)
// ---------------------------------------------------------------------------
__global__ void k_out(const float* __restrict__ bw, float* __restrict__ out) {
    const float IR2 = 0.70710678118654752440f;
    const float C1 = 0.35355339059327376220f;  // 1/(2*sqrt(2))
    int b = blockIdx.y, s = blockIdx.x, t = threadIdx.x;
    const float* rf = g_rhof + b * S;
    int g = s >> 3, k = s & 7;
    float t0 = rf[g] * C1;
    float t1 = rf[256 + g] * ((k < 4) ? C1 : -C1);
    float t2 = rf[512 + 2 * g + (k >> 2)] * (((k >> 1) & 1) ? -0.5f : 0.5f);
    float t3 = rf[1024 + 4 * g + (k >> 1)] * ((k & 1) ? -IR2 : IR2);

    float4* o = (float4*)(out + ((size_t)(b * S + s)) * 2048);
    const float4* b0 = (const float4*)(bw);
    const float4* b1 = (const float4*)(bw + 2048);
    const float4* b2 = (const float4*)(bw + 4096);
    const float4* b3 = (const float4*)(bw + 6144);
#pragma unroll
    for (int j = t; j < 512; j += 256) {
        float4 w0 = b0[j], w1 = b1[j], w2 = b2[j], w3 = b3[j];
        float4 r;
        r.x = t0 * w0.x + t1 * w1.x + t2 * w2.x + t3 * w3.x;
        r.y = t0 * w0.y + t1 * w1.y + t2 * w2.y + t3 * w3.y;
        r.z = t0 * w0.z + t1 * w1.z + t2 * w2.z + t3 * w3.z;
        r.w = t0 * w0.w + t1 * w1.w + t2 * w2.w + t3 * w3.w;
        __stcs(&o[j], r);
    }
}

extern "C" void kernel_launch(void* const* d_in, const int* in_sizes, int n_in,
                              void* d_out, int out_size) {
    const float* x = (const float*)d_in[0];
    const float* wval = (const float*)d_in[1];
    const float* phi = (const float*)d_in[2];
    const float* bw = (const float*)d_in[3];
    float* out = (float*)d_out;

    const int smem_bytes = (14 * S + 64 + 20) * (int)sizeof(float);
    cudaFuncSetAttribute(k_dyn, cudaFuncAttributeMaxDynamicSharedMemorySize, smem_bytes);

    k_reduce<<<dim3(S / 8, BATCH), 256>>>(x, wval);
    k_dyn<<<BATCH, NT, smem_bytes>>>(phi);
    k_out<<<dim3(S, BATCH), 256>>>(bw, out);
}